// round 8
// baseline (speedup 1.0000x reference)
#include <cuda_runtime.h>
#include <cstdint>
#include <cfloat>

#define DL 21
#define SS 512
#define HW (SS*SS)
#define NB 4
#define NE (NB*DL*HW)   // 22,020,096 (~84 MB fp32)

// Spatially transposed unary (b,l,x,y) and edge weights for dirs 0/1
__device__ __align__(16) float g_uT[NE];
__device__ __align__(16) float g_ewT[NB*2*HW];
// Directional results: o0/o1 in transposed space; o2 carries -3u
__device__ __align__(16) float g_o0[NE];
__device__ __align__(16) float g_o1[NE];
__device__ __align__(16) float g_o2[NE];
__device__ __align__(16) float g_o3[NE];

// ---------------------------------------------------------------------------
// Packed f32x2 helpers (fma only — packed min does NOT exist on sm_10x)
typedef unsigned long long u64;
__device__ __forceinline__ u64 f2u(float x, float y) {
    u64 r; asm("mov.b64 %0, {%1, %2};" : "=l"(r) : "f"(x), "f"(y)); return r;
}
__device__ __forceinline__ float2 u2f(u64 v) {
    float2 r; asm("mov.b64 {%0, %1}, %2;" : "=f"(r.x), "=f"(r.y) : "l"(v)); return r;
}
__device__ __forceinline__ u64 ffma2u(u64 a, u64 b, u64 c) {
    u64 d; asm("fma.rn.f32x2 %0, %1, %2, %3;" : "=l"(d) : "l"(a), "l"(b), "l"(c)); return d;
}

// ---------------------------------------------------------------------------
// 32x32 tile transpose using float4, conflict-free padded tile
__device__ __forceinline__ void tr_tile4(const float* __restrict__ sp,
                                         float* __restrict__ dp, int tt, int tid) {
    __shared__ float tile[32][33];
    const int ty0 = (tt >> 4) << 5;
    const int tx0 = (tt & 15) << 5;
    const int r  = tid >> 3;
    const int q4 = (tid & 7) << 2;
    float4 v = __ldcs(reinterpret_cast<const float4*>(sp + (size_t)(ty0 + r) * SS + tx0 + q4));
    tile[r][q4 + 0] = v.x; tile[r][q4 + 1] = v.y;
    tile[r][q4 + 2] = v.z; tile[r][q4 + 3] = v.w;
    __syncthreads();
    float4 o = make_float4(tile[q4 + 0][r], tile[q4 + 1][r],
                           tile[q4 + 2][r], tile[q4 + 3][r]);
    *reinterpret_cast<float4*>(dp + (size_t)(tx0 + r) * SS + ty0 + q4) = o;
}

// planes 0..83: unary; 84..91: edge weights dirs 0/1
__global__ void __launch_bounds__(256)
transpose_all(const float* __restrict__ u, const float* __restrict__ ew) {
    const int plane = blockIdx.x >> 8;
    const int tt = blockIdx.x & 255;
    if (plane < NB * DL) {
        tr_tile4(u + (size_t)plane * HW, g_uT + (size_t)plane * HW, tt, threadIdx.x);
    } else {
        const int p = plane - NB * DL;          // 0..7
        const int b = p >> 1, d = p & 1;
        tr_tile4(ew + (size_t)(b * 4 + d) * HW, g_ewT + (size_t)p * HW, tt, threadIdx.x);
    }
}

// ---------------------------------------------------------------------------
// Sweep: 176-thread block = 16 columns x 11 label-pairs, TWO independent
// (same-dir, different-batch) chains interleaved per block; one barrier per
// step-pair. Depth-2 prefetch, FFMA2-packed fma, scalar min chains.
template<int DIR>
__device__ __forceinline__ void run_sweep2(const float* __restrict__ u,
                                           const float* __restrict__ ew,
                                           int bA, int bB, int cc,
                                           int c, int lg, bool has2, int l0, int l1,
                                           const u64 (&Vp0)[11], const u64 (&Vp1)[11],
                                           u64 (*Lb)[2][16][11]) {
    const float* src = (DIR < 2) ? g_uT : u;
    const float* wsA = (DIR < 2) ? (g_ewT + (size_t)(bA * 2 + DIR) * HW)
                                 : (ew   + (size_t)(bA * 4 + DIR) * HW);
    const float* wsB = (DIR < 2) ? (g_ewT + (size_t)(bB * 2 + DIR) * HW)
                                 : (ew   + (size_t)(bB * 4 + DIR) * HW);
    float* dst = (DIR == 0) ? g_o0 : (DIR == 1) ? g_o1 : (DIR == 2) ? g_o2 : g_o3;
    constexpr int STRD = (DIR == 0 || DIR == 2) ? SS : -SS;
    const int start = (STRD > 0) ? 0 : (SS - 1) * SS;

    const int baseA0 = (bA * DL + l0) * HW + cc;
    const int baseA1 = (bA * DL + l1) * HW + cc;
    const int baseB0 = (bB * DL + l0) * HW + cc;
    const int baseB1 = (bB * DL + l1) * HW + cc;

    float LA0, LA1, LB0, LB1;
    // t = 0 (border: L = u)
    {
        float a0 = __ldg(src + baseA0 + start);
        float a1 = __ldg(src + baseA1 + start);
        float b0 = __ldg(src + baseB0 + start);
        float b1 = __ldg(src + baseB1 + start);
        LA0 = a0; LA1 = a1; LB0 = b0; LB1 = b1;
        __stcs(dst + baseA0 + start, (DIR == 2) ? fmaf(-3.0f, a0, LA0) : LA0);
        if (has2) __stcs(dst + baseA1 + start, (DIR == 2) ? fmaf(-3.0f, a1, LA1) : LA1);
        __stcs(dst + baseB0 + start, (DIR == 2) ? fmaf(-3.0f, b0, LB0) : LB0);
        if (has2) __stcs(dst + baseB1 + start, (DIR == 2) ? fmaf(-3.0f, b1, LB1) : LB1);
        Lb[0][0][c][lg] = f2u(LA0, has2 ? LA1 : FLT_MAX);
        Lb[1][0][c][lg] = f2u(LB0, has2 ? LB1 : FLT_MAX);
    }
    // depth-2 prefetch ring
    int offL = start + STRD;
    float aA0 = __ldg(src + baseA0 + offL), aA1 = __ldg(src + baseA1 + offL);
    float aB0 = __ldg(src + baseB0 + offL), aB1 = __ldg(src + baseB1 + offL);
    float awA = __ldg(wsA + cc + offL),     awB = __ldg(wsB + cc + offL);
    offL += STRD;
    float bA0_ = __ldg(src + baseA0 + offL), bA1_ = __ldg(src + baseA1 + offL);
    float bB0_ = __ldg(src + baseB0 + offL), bB1_ = __ldg(src + baseB1 + offL);
    float bwA = __ldg(wsA + cc + offL),      bwB = __ldg(wsB + cc + offL);
    __syncthreads();

    auto stepf = [&](u64 (*LbP)[16][11], int wp, float u0v, float u1v, float wv,
                     float& L0, float& L1, int b0i, int b1i, int offS) {
        const u64* Lo = LbP[wp ^ 1][c];
        const u64 w2 = f2u(wv, wv);
        u64 xu = Lo[0];
        float2 cA = u2f(ffma2u(w2, Vp0[0], xu));
        float2 cE = u2f(ffma2u(w2, Vp1[0], xu));
        float a0 = cA.x, a1 = cA.y, e0 = cE.x, e1 = cE.y;
#pragma unroll
        for (int kk = 1; kk < 11; kk++) {
            xu = Lo[kk];
            cA = u2f(ffma2u(w2, Vp0[kk], xu));
            cE = u2f(ffma2u(w2, Vp1[kk], xu));
            a0 = fminf(a0, cA.x); a1 = fminf(a1, cA.y);
            e0 = fminf(e0, cE.x); e1 = fminf(e1, cE.y);
        }
        L0 = u0v + fminf(a0, a1);
        L1 = u1v + fminf(e0, e1);
        __stcs(dst + b0i + offS, (DIR == 2) ? fmaf(-3.0f, u0v, L0) : L0);
        if (has2) __stcs(dst + b1i + offS, (DIR == 2) ? fmaf(-3.0f, u1v, L1) : L1);
        LbP[wp][c][lg] = f2u(L0, has2 ? L1 : FLT_MAX);
    };

    int offS = start;
#pragma unroll 1
    for (int t = 1; t <= SS - 3; t++) {
        offS += STRD;
        offL += STRD;
        // issue next loads first so they fly during compute
        float nA0 = __ldg(src + baseA0 + offL), nA1 = __ldg(src + baseA1 + offL);
        float nB0 = __ldg(src + baseB0 + offL), nB1 = __ldg(src + baseB1 + offL);
        float nwA = __ldg(wsA + cc + offL),     nwB = __ldg(wsB + cc + offL);
        stepf(Lb[0], t & 1, aA0, aA1, awA, LA0, LA1, baseA0, baseA1, offS);
        stepf(Lb[1], t & 1, aB0, aB1, awB, LB0, LB1, baseB0, baseB1, offS);
        aA0 = bA0_; aA1 = bA1_; awA = bwA;
        aB0 = bB0_; aB1 = bB1_; awB = bwB;
        bA0_ = nA0; bA1_ = nA1; bwA = nwA;
        bB0_ = nB0; bB1_ = nB1; bwB = nwB;
        __syncthreads();
    }
    // t = SS-2
    offS += STRD;
    stepf(Lb[0], (SS - 2) & 1, aA0, aA1, awA, LA0, LA1, baseA0, baseA1, offS);
    stepf(Lb[1], (SS - 2) & 1, aB0, aB1, awB, LB0, LB1, baseB0, baseB1, offS);
    __syncthreads();
    // t = SS-1
    offS += STRD;
    stepf(Lb[0], (SS - 1) & 1, bA0_, bA1_, bwA, LA0, LA1, baseA0, baseA1, offS);
    stepf(Lb[1], (SS - 1) & 1, bB0_, bB1_, bwB, LB0, LB1, baseB0, baseB1, offS);
}

__global__ void __launch_bounds__(176, 3)
sweep(const float* __restrict__ u, const float* __restrict__ ew,
      const float* __restrict__ lc) {
    __shared__ u64 Lb[2][2][16][11];          // [prob][wp][c][lg]
    const int bx   = blockIdx.x;              // 256 blocks
    const int pair = bx >> 5;                 // 0..7
    const int col0 = (bx & 31) << 4;          // 32 col-groups x 16 cols
    const int dir  = pair >> 1;
    const int bA   = (pair & 1) << 1;         // batches (0,1) or (2,3)
    const int bB   = bA + 1;
    const int c    = threadIdx.x & 15;
    const int lg   = threadIdx.x >> 4;        // 0..10
    const int l0   = 2 * lg;
    const bool has2 = (lg < 10);
    const int l1   = has2 ? l0 + 1 : l0;
    const int cc   = col0 + c;

    // V pairs packed along k (source label): Vp[kk] = {V[2kk][l], V[2kk+1][l]}
    u64 Vp0[11], Vp1[11];
#pragma unroll
    for (int kk = 0; kk < 11; kk++) {
        const int ka = 2 * kk, kb = 2 * kk + 1;
        float va0 = __ldg(lc + ka * DL + l0);
        float vb0 = (kb < DL) ? __ldg(lc + kb * DL + l0) : 0.0f;
        float va1 = __ldg(lc + ka * DL + l1);
        float vb1 = (kb < DL) ? __ldg(lc + kb * DL + l1) : 0.0f;
        Vp0[kk] = f2u(va0, vb0);
        Vp1[kk] = f2u(va1, vb1);
    }

    if (dir == 0)      run_sweep2<0>(u, ew, bA, bB, cc, c, lg, has2, l0, l1, Vp0, Vp1, Lb);
    else if (dir == 1) run_sweep2<1>(u, ew, bA, bB, cc, c, lg, has2, l0, l1, Vp0, Vp1, Lb);
    else if (dir == 2) run_sweep2<2>(u, ew, bA, bB, cc, c, lg, has2, l0, l1, Vp0, Vp1, Lb);
    else               run_sweep2<3>(u, ew, bA, bB, cc, c, lg, has2, l0, l1, Vp0, Vp1, Lb);
}

// ---------------------------------------------------------------------------
// out(b,l,y,x) = o2(y,x) + o3(y,x) + o0(x,y) + o1(x,y)   [o2 carries -3u]
__global__ void __launch_bounds__(256)
combine(float* __restrict__ out) {
    __shared__ float t0[32][33], t1[32][33];
    const int plane = blockIdx.x >> 8;       // b*21+l
    const int tt = blockIdx.x & 255;
    const int y0 = (tt >> 4) << 5;
    const int x0 = (tt & 15) << 5;
    const size_t pb = (size_t)plane * HW;
    const int r  = threadIdx.x >> 3;
    const int q4 = (threadIdx.x & 7) << 2;
    {   // load transposed planes: rows along x, vectorized along y
        size_t idx = pb + (size_t)(x0 + r) * SS + y0 + q4;
        float4 a  = __ldcs(reinterpret_cast<const float4*>(g_o0 + idx));
        float4 bq = __ldcs(reinterpret_cast<const float4*>(g_o1 + idx));
        t0[r][q4 + 0] = a.x;  t0[r][q4 + 1] = a.y;
        t0[r][q4 + 2] = a.z;  t0[r][q4 + 3] = a.w;
        t1[r][q4 + 0] = bq.x; t1[r][q4 + 1] = bq.y;
        t1[r][q4 + 2] = bq.z; t1[r][q4 + 3] = bq.w;
    }
    __syncthreads();
    {   // stream o2/o3 + add transposed tiles, vectorized along x
        size_t idx = pb + (size_t)(y0 + r) * SS + x0 + q4;
        float4 r2 = __ldcs(reinterpret_cast<const float4*>(g_o2 + idx));
        float4 r3 = __ldcs(reinterpret_cast<const float4*>(g_o3 + idx));
        float4 o;
        o.x = r2.x + r3.x + t0[q4 + 0][r] + t1[q4 + 0][r];
        o.y = r2.y + r3.y + t0[q4 + 1][r] + t1[q4 + 1][r];
        o.z = r2.z + r3.z + t0[q4 + 2][r] + t1[q4 + 2][r];
        o.w = r2.w + r3.w + t0[q4 + 3][r] + t1[q4 + 3][r];
        __stcs(reinterpret_cast<float4*>(out + idx), o);
    }
}

// ---------------------------------------------------------------------------
extern "C" void kernel_launch(void* const* d_in, const int* in_sizes, int n_in,
                              void* d_out, int out_size) {
    const float* unary = (const float*)d_in[0];   // (4,1,21,512,512)
    const float* ew    = (const float*)d_in[1];   // (4,4,512,512)
    const float* lc    = (const float*)d_in[2];   // (21,21)
    float* out = (float*)d_out;                   // (4,1,21,512,512)

    transpose_all<<<(NB * DL + NB * 2) * 256, 256>>>(unary, ew);
    sweep<<<256, 176>>>(unary, ew, lc);
    combine<<<NB * DL * 256, 256>>>(out);
}

// round 9
// speedup vs baseline: 1.0946x; 1.0946x over previous
#include <cuda_runtime.h>
#include <cstdint>
#include <cfloat>

#define DL 21
#define SS 512
#define HW (SS*SS)
#define NB 4
#define NE (NB*DL*HW)   // 22,020,096 (~84 MB fp32)

// Spatially transposed unary (b,l,x,y) and edge weights for dirs 0/1
__device__ __align__(16) float g_uT[NE];
__device__ __align__(16) float g_ewT[NB*2*HW];
// Directional results: o0/o1 in transposed space; o2 carries -3u
__device__ __align__(16) float g_o0[NE];
__device__ __align__(16) float g_o1[NE];
__device__ __align__(16) float g_o2[NE];
__device__ __align__(16) float g_o3[NE];

// ---------------------------------------------------------------------------
// Packed f32x2 helpers (fma only — packed min does not exist on sm_10x)
typedef unsigned long long u64;
__device__ __forceinline__ u64 f2u(float x, float y) {
    u64 r; asm("mov.b64 %0, {%1, %2};" : "=l"(r) : "f"(x), "f"(y)); return r;
}
__device__ __forceinline__ float2 u2f(u64 v) {
    float2 r; asm("mov.b64 {%0, %1}, %2;" : "=f"(r.x), "=f"(r.y) : "l"(v)); return r;
}
__device__ __forceinline__ u64 ffma2u(u64 a, u64 b, u64 c) {
    u64 d; asm("fma.rn.f32x2 %0, %1, %2, %3;" : "=l"(d) : "l"(a), "l"(b), "l"(c)); return d;
}

// ---------------------------------------------------------------------------
// 32x32 tile transpose using float4, conflict-free padded tile
__device__ __forceinline__ void tr_tile4(const float* __restrict__ sp,
                                         float* __restrict__ dp, int tt, int tid) {
    __shared__ float tile[32][33];
    const int ty0 = (tt >> 4) << 5;
    const int tx0 = (tt & 15) << 5;
    const int r  = tid >> 3;
    const int q4 = (tid & 7) << 2;
    float4 v = *reinterpret_cast<const float4*>(sp + (size_t)(ty0 + r) * SS + tx0 + q4);
    tile[r][q4 + 0] = v.x; tile[r][q4 + 1] = v.y;
    tile[r][q4 + 2] = v.z; tile[r][q4 + 3] = v.w;
    __syncthreads();
    float4 o = make_float4(tile[q4 + 0][r], tile[q4 + 1][r],
                           tile[q4 + 2][r], tile[q4 + 3][r]);
    *reinterpret_cast<float4*>(dp + (size_t)(tx0 + r) * SS + ty0 + q4) = o;
}

// planes 0..83: unary; 84..91: edge weights dirs 0/1
__global__ void __launch_bounds__(256)
transpose_all(const float* __restrict__ u, const float* __restrict__ ew) {
    const int plane = blockIdx.x >> 8;
    const int tt = blockIdx.x & 255;
    if (plane < NB * DL) {
        tr_tile4(u + (size_t)plane * HW, g_uT + (size_t)plane * HW, tt, threadIdx.x);
    } else {
        const int p = plane - NB * DL;          // 0..7
        const int b = p >> 1, d = p & 1;
        tr_tile4(ew + (size_t)(b * 4 + d) * HW, g_ewT + (size_t)p * HW, tt, threadIdx.x);
    }
}

// ---------------------------------------------------------------------------
// Sweep: block = 32 columns x 11 label-pair warps, smem L-exchange,
// depth-2 prefetch, packed FFMA2 inner loop.
// Lb layout [wp][kk][c] (c innermost): LDS.64/STS.64 read/write 256B
// contiguous per warp -> conflict-free (old [c][lg] layout had a 2-way
// bank conflict: 88B stride * 16 lanes = 1408B = 0 mod 128).
template<int DIR>
__device__ __forceinline__ void run_sweep(const float* __restrict__ u,
                                          const float* __restrict__ ew,
                                          int b, int col0, int c, int lg,
                                          bool has2, int base0, int base1,
                                          const u64 (&Vp0)[11],
                                          const u64 (&Vp1)[11],
                                          u64 (*Lb)[11][32]) {
    const float* src  = (DIR < 2) ? g_uT : u;
    const float* wsrc = (DIR < 2) ? (g_ewT + (size_t)(b * 2 + DIR) * HW)
                                  : (ew   + (size_t)(b * 4 + DIR) * HW);
    float* dst = (DIR == 0) ? g_o0 : (DIR == 1) ? g_o1 : (DIR == 2) ? g_o2 : g_o3;
    constexpr int STRD = (DIR == 0 || DIR == 2) ? SS : -SS;
    const int start = (STRD > 0) ? 0 : (SS - 1) * SS;
    const int wb = col0 + c;

    float L0, L1;
    int offL = start;
    // t = 0 (border: L = u)
    {
        float cu0 = __ldg(src + base0 + offL);
        float cu1 = __ldg(src + base1 + offL);
        L0 = cu0; L1 = cu1;
        dst[base0 + offL] = (DIR == 2) ? fmaf(-3.0f, cu0, L0) : L0;
        if (has2) dst[base1 + offL] = (DIR == 2) ? fmaf(-3.0f, cu1, L1) : L1;
        Lb[0][lg][c] = f2u(L0, has2 ? L1 : FLT_MAX);
    }
    // prefetch t = 1, t = 2
    offL += STRD;
    float au0 = __ldg(src + base0 + offL);
    float au1 = __ldg(src + base1 + offL);
    float aw  = __ldg(wsrc + wb + offL);
    offL += STRD;
    float bu0 = __ldg(src + base0 + offL);
    float bu1 = __ldg(src + base1 + offL);
    float bw  = __ldg(wsrc + wb + offL);
    __syncthreads();

    auto stepf = [&](int wp, float u0v, float u1v, float wv, int offS) {
        const u64 (*Lo)[32] = Lb[wp ^ 1];
        const u64 w2 = f2u(wv, wv);
        u64 xu = Lo[0][c];
        float2 cA = u2f(ffma2u(w2, Vp0[0], xu));
        float2 cE = u2f(ffma2u(w2, Vp1[0], xu));
        float a0 = cA.x, a1 = cA.y, e0 = cE.x, e1 = cE.y;
#pragma unroll
        for (int kk = 1; kk < 11; kk++) {
            xu = Lo[kk][c];
            cA = u2f(ffma2u(w2, Vp0[kk], xu));
            cE = u2f(ffma2u(w2, Vp1[kk], xu));
            a0 = fminf(a0, cA.x); a1 = fminf(a1, cA.y);
            e0 = fminf(e0, cE.x); e1 = fminf(e1, cE.y);
        }
        L0 = u0v + fminf(a0, a1);
        L1 = u1v + fminf(e0, e1);
        dst[base0 + offS] = (DIR == 2) ? fmaf(-3.0f, u0v, L0) : L0;
        if (has2) dst[base1 + offS] = (DIR == 2) ? fmaf(-3.0f, u1v, L1) : L1;
        Lb[wp][lg][c] = f2u(L0, has2 ? L1 : FLT_MAX);
    };

    int offS = start;
#pragma unroll 1
    for (int t = 1; t <= SS - 3; t++) {
        offS += STRD;
        stepf(t & 1, au0, au1, aw, offS);
        au0 = bu0; au1 = bu1; aw = bw;
        offL += STRD;
        bu0 = __ldg(src + base0 + offL);
        bu1 = __ldg(src + base1 + offL);
        bw  = __ldg(wsrc + wb + offL);
        __syncthreads();
    }
    // t = SS-2
    offS += STRD;
    stepf((SS - 2) & 1, au0, au1, aw, offS);
    au0 = bu0; au1 = bu1; aw = bw;
    __syncthreads();
    // t = SS-1
    offS += STRD;
    stepf((SS - 1) & 1, au0, au1, aw, offS);
}

__global__ void __launch_bounds__(352, 2)
sweep(const float* __restrict__ u, const float* __restrict__ ew,
      const float* __restrict__ lc) {
    __shared__ u64 Lb[2][11][32];
    const int bx   = blockIdx.x;
    const int dir  = bx >> 6;
    const int b    = (bx >> 4) & 3;
    const int col0 = (bx & 15) << 5;
    const int c    = threadIdx.x & 31;
    const int lg   = threadIdx.x >> 5;
    const int l0   = 2 * lg;
    const bool has2 = (lg < 10);
    const int l1   = has2 ? l0 + 1 : l0;

    // V pairs packed along k (source label): Vp[kk] = {V[2kk][l], V[2kk+1][l]}
    u64 Vp0[11], Vp1[11];
#pragma unroll
    for (int kk = 0; kk < 11; kk++) {
        const int ka = 2 * kk, kb = 2 * kk + 1;
        float va0 = __ldg(lc + ka * DL + l0);
        float vb0 = (kb < DL) ? __ldg(lc + kb * DL + l0) : 0.0f;
        float va1 = __ldg(lc + ka * DL + l1);
        float vb1 = (kb < DL) ? __ldg(lc + kb * DL + l1) : 0.0f;
        Vp0[kk] = f2u(va0, vb0);
        Vp1[kk] = f2u(va1, vb1);
    }

    const int base0 = (b * DL + l0) * HW + col0 + c;
    const int base1 = (b * DL + l1) * HW + col0 + c;

    if (dir == 0)      run_sweep<0>(u, ew, b, col0, c, lg, has2, base0, base1, Vp0, Vp1, Lb);
    else if (dir == 1) run_sweep<1>(u, ew, b, col0, c, lg, has2, base0, base1, Vp0, Vp1, Lb);
    else if (dir == 2) run_sweep<2>(u, ew, b, col0, c, lg, has2, base0, base1, Vp0, Vp1, Lb);
    else               run_sweep<3>(u, ew, b, col0, c, lg, has2, base0, base1, Vp0, Vp1, Lb);
}

// ---------------------------------------------------------------------------
// out(b,l,y,x) = o2(y,x) + o3(y,x) + o0(x,y) + o1(x,y)   [o2 carries -3u]
__global__ void __launch_bounds__(256)
combine(float* __restrict__ out) {
    __shared__ float t0[32][33], t1[32][33];
    const int plane = blockIdx.x >> 8;       // b*21+l
    const int tt = blockIdx.x & 255;
    const int y0 = (tt >> 4) << 5;
    const int x0 = (tt & 15) << 5;
    const size_t pb = (size_t)plane * HW;
    const int r  = threadIdx.x >> 3;
    const int q4 = (threadIdx.x & 7) << 2;
    {   // load transposed planes: rows along x, vectorized along y
        size_t idx = pb + (size_t)(x0 + r) * SS + y0 + q4;
        float4 a = *reinterpret_cast<const float4*>(g_o0 + idx);
        float4 bq = *reinterpret_cast<const float4*>(g_o1 + idx);
        t0[r][q4 + 0] = a.x;  t0[r][q4 + 1] = a.y;
        t0[r][q4 + 2] = a.z;  t0[r][q4 + 3] = a.w;
        t1[r][q4 + 0] = bq.x; t1[r][q4 + 1] = bq.y;
        t1[r][q4 + 2] = bq.z; t1[r][q4 + 3] = bq.w;
    }
    __syncthreads();
    {   // stream o2/o3 + add transposed tiles, vectorized along x
        size_t idx = pb + (size_t)(y0 + r) * SS + x0 + q4;
        float4 r2 = *reinterpret_cast<const float4*>(g_o2 + idx);
        float4 r3 = *reinterpret_cast<const float4*>(g_o3 + idx);
        float4 o;
        o.x = r2.x + r3.x + t0[q4 + 0][r] + t1[q4 + 0][r];
        o.y = r2.y + r3.y + t0[q4 + 1][r] + t1[q4 + 1][r];
        o.z = r2.z + r3.z + t0[q4 + 2][r] + t1[q4 + 2][r];
        o.w = r2.w + r3.w + t0[q4 + 3][r] + t1[q4 + 3][r];
        *reinterpret_cast<float4*>(out + idx) = o;
    }
}

// ---------------------------------------------------------------------------
extern "C" void kernel_launch(void* const* d_in, const int* in_sizes, int n_in,
                              void* d_out, int out_size) {
    const float* unary = (const float*)d_in[0];   // (4,1,21,512,512)
    const float* ew    = (const float*)d_in[1];   // (4,4,512,512)
    const float* lc    = (const float*)d_in[2];   // (21,21)
    float* out = (float*)d_out;                   // (4,1,21,512,512)

    transpose_all<<<(NB * DL + NB * 2) * 256, 256>>>(unary, ew);
    sweep<<<256, 352>>>(unary, ew, lc);
    combine<<<NB * DL * 256, 256>>>(out);
}